// round 17
// baseline (speedup 1.0000x reference)
#include <cuda_runtime.h>
#include <cstdint>

#define MAX_SAMPLES 512
#define TPB 1024
#define SEGS 7
#define SEG_PTS (TPB * 4)          // 4096
#define W (SEGS * SEG_PTS)         // 28672-pt window (fill pt +7.6 sigma)
#define MAXB 64

// Match XLA's non-contracted, left-associated ((x*x)+(y*y))+(z*z).
__device__ __forceinline__ unsigned octant_of(float x, float y, float z) {
    float r2 = __fadd_rn(__fadd_rn(__fmul_rn(x, x), __fmul_rn(y, y)), __fmul_rn(z, z));
    if (!(r2 <= 1.0f)) return 0xFu;
    return ((x >= 0.0f) ? 4u : 0u) | ((y >= 0.0f) ? 2u : 0u) | ((z >= 0.0f) ? 1u : 0u);
}

__device__ __forceinline__ unsigned classify4(const float* __restrict__ xs,
                                              const float* __restrict__ ys,
                                              const float* __restrict__ zs,
                                              int i0, int N) {
    float px[4], py[4], pz[4];
    if (i0 + 3 < N && (N & 3) == 0) {
        const float4 vx = *reinterpret_cast<const float4*>(xs + i0);
        const float4 vy = *reinterpret_cast<const float4*>(ys + i0);
        const float4 vz = *reinterpret_cast<const float4*>(zs + i0);
        px[0] = vx.x; px[1] = vx.y; px[2] = vx.z; px[3] = vx.w;
        py[0] = vy.x; py[1] = vy.y; py[2] = vy.z; py[3] = vy.w;
        pz[0] = vz.x; pz[1] = vz.y; pz[2] = vz.z; pz[3] = vz.w;
    } else {
#pragma unroll
        for (int j = 0; j < 4; j++) {
            const int ii = i0 + j;
            const bool ok = (ii < N);
            px[j] = ok ? xs[ii] : 2.0f;   // sentinel: outside ball
            py[j] = ok ? ys[ii] : 2.0f;
            pz[j] = ok ? zs[ii] : 2.0f;
        }
    }
    unsigned word = 0;
#pragma unroll
    for (int j = 0; j < 4; j++)
        word |= octant_of(px[j], py[j], pz[j]) << (4 * j);
    return word;
}

__device__ __forceinline__ void count_word(unsigned word, unsigned& clo,
                                           unsigned& chi, unsigned& lrp) {
    clo = 0; chi = 0; lrp = 0;
#pragma unroll
    for (int j = 0; j < 4; j++) {
        const unsigned o = (word >> (4 * j)) & 0xFu;
        if (o < 8u) {
            const unsigned sh  = 8u * (o & 3u);
            const unsigned cur = (o < 4u) ? clo : chi;
            lrp |= ((cur >> sh) & 3u) << (2 * j);
            if (o < 4u) clo += 1u << sh; else chi += 1u << sh;
        }
    }
}

// ---------------------------------------------------------------------------
// Zero-communication fused kernel. Block (b,seg) RECOUNTS all points before
// its segment itself (L2-resident across replays; redundancy is cheaper than
// inter-block waiting, per R15/R16), then classifies + ranks + writes its own
// 4096-pt segment. No flags, no lookback, no scratch, one launch.
// ---------------------------------------------------------------------------
__global__ __launch_bounds__(TPB, 1)
void recount_kernel(const float* __restrict__ pcs, float* __restrict__ out, int N) {
    const int b    = blockIdx.x / SEGS;
    const int seg  = blockIdx.x % SEGS;
    const int tid  = threadIdx.x;
    const int lane = tid & 31;
    const int w    = tid >> 5;

    const float* __restrict__ xs = pcs + (size_t)b * 3 * N;
    const float* __restrict__ ys = xs + N;
    const float* __restrict__ zs = ys + N;
    float* __restrict__ out_b = out + (size_t)b * (8 * MAX_SAMPLES);

    __shared__ unsigned smp[32][4];     // pred warp sums (packed-16 x4)
    __shared__ unsigned sm_ws[32][2];
    __shared__ unsigned sm_off[32][4];
    __shared__ unsigned sh_totw[4];
    __shared__ int sh_gbase[8];

    // ---- 1) recount predecessors (seg rounds, 2-deep software pipeline) ----
    unsigned plo = 0, phi = 0;          // packed byte counters (<=24/thread)
    {
        unsigned wd_next = 0;
        if (seg > 0) wd_next = classify4(xs, ys, zs, tid * 4, N);
        for (int g = 0; g < seg; g++) {
            const unsigned wd = wd_next;
            if (g + 1 < seg)
                wd_next = classify4(xs, ys, zs, (g + 1) * SEG_PTS + tid * 4, N);
#pragma unroll
            for (int j = 0; j < 4; j++) {
                const unsigned o = (wd >> (4 * j)) & 0xFu;
                if (o < 8u) {
                    if (o < 4u) plo += 1u << (8 * o);
                    else        phi += 1u << (8 * (o - 4));
                }
            }
        }
    }
    // expand bytes -> packed-16 (warp sums up to 768 need 16 bits)
    unsigned p0 = (plo & 0xFFu)          | (((plo >> 8)  & 0xFFu) << 16);
    unsigned p1 = ((plo >> 16) & 0xFFu)  | (((plo >> 24) & 0xFFu) << 16);
    unsigned p2 = (phi & 0xFFu)          | (((phi >> 8)  & 0xFFu) << 16);
    unsigned p3 = ((phi >> 16) & 0xFFu)  | (((phi >> 24) & 0xFFu) << 16);
#pragma unroll
    for (int off = 16; off > 0; off >>= 1) {
        p0 += __shfl_down_sync(0xFFFFFFFFu, p0, off);
        p1 += __shfl_down_sync(0xFFFFFFFFu, p1, off);
        p2 += __shfl_down_sync(0xFFFFFFFFu, p2, off);
        p3 += __shfl_down_sync(0xFFFFFFFFu, p3, off);
    }
    if (lane == 0) { smp[w][0] = p0; smp[w][1] = p1; smp[w][2] = p2; smp[w][3] = p3; }
    __syncthreads();

    if (w < 8) {   // warp w reduces octant w across the 32 warps
        int v = (int)((smp[lane][w >> 1] >> (16 * (w & 1))) & 0xFFFFu);
#pragma unroll
        for (int off = 16; off > 0; off >>= 1)
            v += __shfl_down_sync(0xFFFFFFFFu, v, off);
        if (lane == 0) sh_gbase[w] = v;
    }
    __syncthreads();

    {
        bool full = true;
#pragma unroll
        for (int q = 0; q < 8; q++) full = full && (sh_gbase[q] >= MAX_SAMPLES);
        if (full) return;   // all slots already written by earlier segments
    }

    const bool last = (seg == SEGS - 1);

    // ---- 2) own segment (iter 0) + dormant tail (last seg only) ----
    for (int iter = 0; ; iter++) {
        const int pbase = (iter == 0) ? seg * SEG_PTS : W + (iter - 1) * SEG_PTS;
        if (iter > 0 && pbase >= N) break;

        const unsigned word = classify4(xs, ys, zs, pbase + tid * 4, N);
        unsigned clo, chi, lrp;
        count_word(word, clo, chi, lrp);

        unsigned slo = clo, shi = chi;
#pragma unroll
        for (int d = 1; d < 32; d <<= 1) {
            const unsigned tlo = __shfl_up_sync(0xFFFFFFFFu, slo, d);
            const unsigned thi = __shfl_up_sync(0xFFFFFFFFu, shi, d);
            if (lane >= d) { slo += tlo; shi += thi; }
        }
        if (lane == 31) { sm_ws[w][0] = slo; sm_ws[w][1] = shi; }
        __syncthreads();                                   // (A)

        if (w == 0) {
            const unsigned alo = sm_ws[lane][0], ahi = sm_ws[lane][1];
            unsigned t0 = (alo & 0xFFu)         | (((alo >> 8)  & 0xFFu) << 16);
            unsigned t1 = ((alo >> 16) & 0xFFu) | (((alo >> 24) & 0xFFu) << 16);
            unsigned t2 = (ahi & 0xFFu)         | (((ahi >> 8)  & 0xFFu) << 16);
            unsigned t3 = ((ahi >> 16) & 0xFFu) | (((ahi >> 24) & 0xFFu) << 16);
            const unsigned o0 = t0, o1 = t1, o2 = t2, o3 = t3;
#pragma unroll
            for (int d = 1; d < 32; d <<= 1) {
                const unsigned u0 = __shfl_up_sync(0xFFFFFFFFu, t0, d);
                const unsigned u1 = __shfl_up_sync(0xFFFFFFFFu, t1, d);
                const unsigned u2 = __shfl_up_sync(0xFFFFFFFFu, t2, d);
                const unsigned u3 = __shfl_up_sync(0xFFFFFFFFu, t3, d);
                if (lane >= d) { t0 += u0; t1 += u1; t2 += u2; t3 += u3; }
            }
            sm_off[lane][0] = t0 - o0; sm_off[lane][1] = t1 - o1;
            sm_off[lane][2] = t2 - o2; sm_off[lane][3] = t3 - o3;
            if (lane == 31) {
                sh_totw[0] = t0; sh_totw[1] = t1; sh_totw[2] = t2; sh_totw[3] = t3;
            }
        }
        __syncthreads();                                   // (B)

        const unsigned elo = slo - clo, ehi = shi - chi;
        const unsigned f0 = sm_off[w][0], f1 = sm_off[w][1];
        const unsigned f2 = sm_off[w][2], f3 = sm_off[w][3];
        const unsigned g0 = sh_totw[0], g1 = sh_totw[1];
        const unsigned g2 = sh_totw[2], g3 = sh_totw[3];

        int tot[8], off[8];
        tot[0] = (int)(g0 & 0xFFFFu); tot[1] = (int)(g0 >> 16);
        tot[2] = (int)(g1 & 0xFFFFu); tot[3] = (int)(g1 >> 16);
        tot[4] = (int)(g2 & 0xFFFFu); tot[5] = (int)(g2 >> 16);
        tot[6] = (int)(g3 & 0xFFFFu); tot[7] = (int)(g3 >> 16);
        off[0] = (int)(f0 & 0xFFFFu) + (int)(elo & 0xFFu);
        off[1] = (int)(f0 >> 16)     + (int)((elo >> 8)  & 0xFFu);
        off[2] = (int)(f1 & 0xFFFFu) + (int)((elo >> 16) & 0xFFu);
        off[3] = (int)(f1 >> 16)     + (int)(elo >> 24);
        off[4] = (int)(f2 & 0xFFFFu) + (int)(ehi & 0xFFu);
        off[5] = (int)(f2 >> 16)     + (int)((ehi >> 8)  & 0xFFu);
        off[6] = (int)(f3 & 0xFFFFu) + (int)((ehi >> 16) & 0xFFu);
        off[7] = (int)(f3 >> 16)     + (int)(ehi >> 24);

        int base[8];
        bool nf = true;
#pragma unroll
        for (int q = 0; q < 8; q++) {
            base[q] = sh_gbase[q] + off[q];
            nf = nf && (sh_gbase[q] + tot[q] >= MAX_SAMPLES);
        }
        __syncthreads();                                   // (C)
        if (tid < 8) sh_gbase[tid] += tot[tid];

        // ordered writes (thread order == index order; base = snapshot)
#pragma unroll
        for (int j = 0; j < 4; j++) {
            const unsigned o = (word >> (4 * j)) & 0xFu;
            if (o < 8u) {
                const int rk = base[o] + (int)((lrp >> (2 * j)) & 3u);
                if (rk < MAX_SAMPLES)
                    out_b[((int)o << 9) + rk] = (float)(pbase + tid * 4 + j);
            }
        }

        if (!last) return;        // non-last segments: exactly one round
        if (nf) break;            // last: everything satisfied
        __syncthreads();          // (D)
    }

    // ---- 3) last block only: fill slots rk >= final totals with -1 ----
    __syncthreads();
    int fin[8];
#pragma unroll
    for (int q = 0; q < 8; q++) fin[q] = sh_gbase[q];
#pragma unroll
    for (int s = 0; s < (8 * MAX_SAMPLES) / TPB; s++) {
        const int idx = s * TPB + tid;
        const int q = idx >> 9;
        const int rk = idx & (MAX_SAMPLES - 1);
        if (rk >= fin[q]) out_b[idx] = -1.0f;
    }
}

// ---------------------------------------------------------------------------
extern "C" void kernel_launch(void* const* d_in, const int* in_sizes, int n_in,
                              void* d_out, int out_size) {
    const float* pcs = (const float*)d_in[0];
    float* out = (float*)d_out;

    int B = out_size / (8 * MAX_SAMPLES);   // 16
    if (B < 1) B = 1;
    if (B > MAXB) B = MAXB;
    int N = in_sizes[0] / (3 * B);          // 200000

    recount_kernel<<<B * SEGS, TPB>>>(pcs, out, N);
}